// round 13
// baseline (speedup 1.0000x reference)
#include <cuda_runtime.h>
#include <cuda_fp16.h>
#include <cstdint>

#define S_LEN  2048
#define BATCH  2
#define HID    1024
#define NHEAD  16
#define HDIM   64
#define NLAYER 12
#define M_ROWS (S_LEN*BATCH)   // 4096
#define ROWB   (BATCH*HID)     // 2048
#define NELEM  (M_ROWS*HID)
#define WELEM  (NLAYER*HID*HID)

typedef __half h16;

// ---------------- scratch ----------------
__device__ float g_x [NELEM];
__device__ float g_y [NELEM];
__device__ float g_m2[BATCH*S_LEN];        // mask * log2e
__device__ h16  g_xh[NELEM];
__device__ h16  g_qh[NELEM];
__device__ h16  g_kh[NELEM];
__device__ h16  g_vh[NELEM];
__device__ h16  g_ch[NELEM];
__device__ h16  g_w [4ull*WELEM];

// ---------------- helpers ----------------
__device__ __forceinline__ uint32_t smem_u32(const void* p) {
    return (uint32_t)__cvta_generic_to_shared(p);
}
__device__ __forceinline__ void cp16(void* s, const void* g) {
    asm volatile("cp.async.cg.shared.global [%0], [%1], 16;"
        :: "r"(smem_u32(s)), "l"(g));
}
#define CP_COMMIT asm volatile("cp.async.commit_group;")
#define CP_WAIT(N) asm volatile("cp.async.wait_group %0;" :: "n"(N))

__device__ __forceinline__ void ldsm4(uint32_t a, uint32_t& r0, uint32_t& r1, uint32_t& r2, uint32_t& r3) {
    asm volatile("ldmatrix.sync.aligned.m8n8.x4.shared.b16 {%0,%1,%2,%3},[%4];"
        : "=r"(r0), "=r"(r1), "=r"(r2), "=r"(r3) : "r"(a));
}
__device__ __forceinline__ void ldsm4t(uint32_t a, uint32_t& r0, uint32_t& r1, uint32_t& r2, uint32_t& r3) {
    asm volatile("ldmatrix.sync.aligned.m8n8.x4.trans.shared.b16 {%0,%1,%2,%3},[%4];"
        : "=r"(r0), "=r"(r1), "=r"(r2), "=r"(r3) : "r"(a));
}
__device__ __forceinline__ void mma16816(float* c, uint32_t a0, uint32_t a1, uint32_t a2, uint32_t a3,
                                         uint32_t b0, uint32_t b1) {
    asm volatile("mma.sync.aligned.m16n8k16.row.col.f32.f16.f16.f32 "
        "{%0,%1,%2,%3},{%4,%5,%6,%7},{%8,%9},{%0,%1,%2,%3};"
        : "+f"(c[0]), "+f"(c[1]), "+f"(c[2]), "+f"(c[3])
        : "r"(a0), "r"(a1), "r"(a2), "r"(a3), "r"(b0), "r"(b1));
}
__device__ __forceinline__ float fexp2(float x) {
    float r;
    asm("ex2.approx.ftz.f32 %0, %1;" : "=f"(r) : "f"(x));
    return r;
}
__device__ __forceinline__ uint32_t fpack2(float x, float y) {
    __half2 p = __floats2half2_rn(x, y);
    return *reinterpret_cast<uint32_t*>(&p);
}

#define LOG2E 1.4426950408889634f
#define SCL2  (0.125f * LOG2E)

// =================================================================
// fp16 GEMM: 256 thr (8 warps, 2m x 4n), warp 64x32, K-tile 64,
// cp.async double-buffered. Same per-warp register budget as R11.
// =================================================================
#define ASTR 72
#define BSTR 136
#define G_A_STAGE (128*ASTR)
#define G_B_STAGE (64*BSTR)
#define SA_OFF(st) ((st)*G_A_STAGE)
#define SB_BASE (2*G_A_STAGE)
#define SB_OFF(st) (SB_BASE + (st)*G_B_STAGE)
#define GEMM_SMEM ((2*(G_A_STAGE + G_B_STAGE))*(int)sizeof(h16))  // 71680

__device__ __forceinline__ void gemm_issue(
    h16* dsm, const h16* __restrict__ A, const h16* __restrict__ W,
    int m0, int n0, int k0, int st, int t)
{
    // A: 128 rows x 64 cols, 2 threads/row, 64B each
    const int ar = t >> 1, ac = (t & 1) * 32;
    const size_t ga = (size_t)(m0 + ar) * HID + k0 + ac;
    h16* a0 = dsm + SA_OFF(st) + ar * ASTR + ac;
    cp16(a0,      A + ga);      cp16(a0 + 8,  A + ga + 8);
    cp16(a0 + 16, A + ga + 16); cp16(a0 + 24, A + ga + 24);
    // B: 64 rows x 128 cols, 4 threads/row, 64B each
    const int br = t >> 2, bc = (t & 3) * 32;
    const size_t gb = (size_t)(k0 + br) * HID + n0 + bc;
    h16* b0 = dsm + SB_OFF(st) + br * BSTR + bc;
    cp16(b0,      W + gb);      cp16(b0 + 8,  W + gb + 8);
    cp16(b0 + 16, W + gb + 16); cp16(b0 + 24, W + gb + 24);
}

__device__ __forceinline__ void gemm_core(
    const h16* __restrict__ A, const h16* __restrict__ W, float acc[4][4][4])
{
    extern __shared__ h16 dsm[];
    const int t = threadIdx.x;
    const int L = t & 31, w = t >> 5;
    const int wm = (w >> 2) * 64, wn = (w & 3) * 32;
    const int m0 = blockIdx.y * 128, n0 = blockIdx.x * 128;

#pragma unroll
    for (int i = 0; i < 4; i++)
#pragma unroll
        for (int j = 0; j < 4; j++)
#pragma unroll
            for (int r = 0; r < 4; r++) acc[i][j][r] = 0.f;

    gemm_issue(dsm, A, W, m0, n0, 0,  0, t); CP_COMMIT;
    gemm_issue(dsm, A, W, m0, n0, 64, 1, t); CP_COMMIT;

    for (int ko = 0; ko < HID / 64; ko++) {
        CP_WAIT(1);
        __syncthreads();
        const int st = ko & 1;
        const h16* cA = dsm + SA_OFF(st);
        const h16* cB = dsm + SB_OFF(st);
#pragma unroll
        for (int ks = 0; ks < 4; ks++) {
            const int kk = ks * 16;
            uint32_t bb[2][4];
#pragma unroll
            for (int nh = 0; nh < 2; nh++) {
                const int brow = kk + (L & 15);
                const int bcol = wn + nh * 16 + ((L >> 4) << 3);
                ldsm4t(smem_u32(cB + brow * BSTR + bcol), bb[nh][0], bb[nh][1], bb[nh][2], bb[nh][3]);
            }
#pragma unroll
            for (int mf = 0; mf < 4; mf++) {
                const int arow = wm + mf * 16 + (L & 15);
                const int acol = kk + ((L >> 4) << 3);
                uint32_t a0, a1, a2, a3;
                ldsm4(smem_u32(cA + arow * ASTR + acol), a0, a1, a2, a3);
#pragma unroll
                for (int nf = 0; nf < 4; nf++) {
                    uint32_t b0 = bb[nf >> 1][(nf & 1) * 2], b1 = bb[nf >> 1][(nf & 1) * 2 + 1];
                    mma16816(acc[mf][nf], a0, a1, a2, a3, b0, b1);
                }
            }
        }
        __syncthreads();
        if (ko + 2 < HID / 64)
            gemm_issue(dsm, A, W, m0, n0, (ko + 2) * 64, st, t);
        CP_COMMIT;
    }
}

// z=0: Q output, scaled by SCL2. z=1: K. z=2: V.
__global__ __launch_bounds__(256, 2)
void qkv_kernel(const h16* __restrict__ xh,
                const h16* __restrict__ wbase,
                const float* __restrict__ bq, const float* __restrict__ bk, const float* __restrict__ bv,
                h16* __restrict__ qh, h16* __restrict__ kh, h16* __restrict__ vh)
{
    const int z = blockIdx.z;
    const h16* W = wbase + (size_t)z * NLAYER * HID * HID;
    const float* bias = (z == 0) ? bq : (z == 1) ? bk : bv;
    h16* out = (z == 0) ? qh : (z == 1) ? kh : vh;
    const float scl = (z == 0) ? SCL2 : 1.0f;

    float acc[4][4][4];
    gemm_core(xh, W, acc);

    const int t = threadIdx.x, L = t & 31, w = t >> 5;
    const int wm = (w >> 2) * 64, wn = (w & 3) * 32;
    const int m0 = blockIdx.y * 128, n0 = blockIdx.x * 128;
#pragma unroll
    for (int mf = 0; mf < 4; mf++) {
        const int r0 = m0 + wm + mf * 16 + (L >> 2);
#pragma unroll
        for (int nf = 0; nf < 4; nf++) {
            const int c = n0 + wn + nf * 8 + 2 * (L & 3);
            const float b0 = bias[c], b1 = bias[c + 1];
            *(uint32_t*)&out[(size_t)r0 * HID + c] =
                fpack2((acc[mf][nf][0] + b0) * scl, (acc[mf][nf][1] + b1) * scl);
            *(uint32_t*)&out[(size_t)(r0 + 8) * HID + c] =
                fpack2((acc[mf][nf][2] + b0) * scl, (acc[mf][nf][3] + b1) * scl);
        }
    }
}

__global__ __launch_bounds__(256, 2)
void oproj_kernel(const h16* __restrict__ ch_, const h16* __restrict__ W,
                  const float* __restrict__ bias, const float* __restrict__ res,
                  float* __restrict__ y)
{
    float acc[4][4][4];
    gemm_core(ch_, W, acc);

    const int t = threadIdx.x, L = t & 31, w = t >> 5;
    const int wm = (w >> 2) * 64, wn = (w & 3) * 32;
    const int m0 = blockIdx.y * 128, n0 = blockIdx.x * 128;
#pragma unroll
    for (int mf = 0; mf < 4; mf++) {
        const int r0 = m0 + wm + mf * 16 + (L >> 2);
#pragma unroll
        for (int nf = 0; nf < 4; nf++) {
            const int c = n0 + wn + nf * 8 + 2 * (L & 3);
            const float b0 = bias[c], b1 = bias[c + 1];
            float2 rv0 = *(const float2*)&res[(size_t)r0 * HID + c];
            float2 rv1 = *(const float2*)&res[(size_t)(r0 + 8) * HID + c];
            float2 o0 = { acc[mf][nf][0] + b0 + rv0.x, acc[mf][nf][1] + b1 + rv0.y };
            float2 o1 = { acc[mf][nf][2] + b0 + rv1.x, acc[mf][nf][3] + b1 + rv1.y };
            *(float2*)&y[(size_t)r0 * HID + c]       = o0;
            *(float2*)&y[(size_t)(r0 + 8) * HID + c] = o1;
        }
    }
}

// =================================================================
// Flash attention fp16 (EXACT R11): 256 thr (8 warps), 16 Q rows/warp,
// QT=128, K-tile 64, 2-stage cp.async KV pipeline, skip-max softmax.
// =================================================================
#define TSTR 72
#define QT   128
#define AT_Q  0
#define AT_ST(st) (QT*TSTR + (st)*2*64*TSTR)
#define AT_V  (64*TSTR)
#define ATTN_SMEM ((QT*TSTR + 4*64*TSTR)*(int)sizeof(h16))  // 55296

__device__ __forceinline__ void attn_issue_kv(
    h16* dsm, const h16* __restrict__ kh, const h16* __restrict__ vh,
    int kt, int st, int base, int t)
{
    const int row = t >> 2, c4 = (t & 3) * 16;
    const size_t g = (size_t)(kt * 64 + row) * ROWB + base + c4;
    h16* s = dsm + AT_ST(st);
    h16* pk = s +        row * TSTR + c4;
    h16* pv = s + AT_V + row * TSTR + c4;
    cp16(pk, kh + g); cp16(pk + 8, kh + g + 8);
    cp16(pv, vh + g); cp16(pv + 8, vh + g + 8);
}

__global__ __launch_bounds__(256, 2)
void attn_f16(const h16* __restrict__ qh,
              const h16* __restrict__ kh, const h16* __restrict__ vh,
              const float* __restrict__ m2,
              h16* __restrict__ ch_)
{
    extern __shared__ h16 dsm[];
    const int t = threadIdx.x, L = t & 31, w = t >> 5;
    const int s0 = blockIdx.x * QT;
    const int b  = blockIdx.y >> 4, h = blockIdx.y & 15;
    const int base = b * HID + h * HDIM;

    {
        const int row = t >> 1, cc = (t & 1) * 32;
        const size_t g = (size_t)(s0 + row) * ROWB + base + cc;
        h16* pq = dsm + AT_Q + row * TSTR + cc;
#pragma unroll
        for (int c = 0; c < 4; c++)
            cp16(pq + c * 8, qh + g + c * 8);
    }
    CP_COMMIT;
    attn_issue_kv(dsm, kh, vh, 0, 0, base, t); CP_COMMIT;
    attn_issue_kv(dsm, kh, vh, 1, 1, base, t); CP_COMMIT;

    CP_WAIT(2);
    __syncthreads();

    uint32_t qf[4][4];
#pragma unroll
    for (int ks = 0; ks < 4; ks++) {
        const int qrow = w * 16 + (L & 15);
        const int qcol = ks * 16 + ((L >> 4) << 3);
        ldsm4(smem_u32(dsm + AT_Q + qrow * TSTR + qcol), qf[ks][0], qf[ks][1], qf[ks][2], qf[ks][3]);
    }

    float oacc[8][4];
#pragma unroll
    for (int i = 0; i < 8; i++)
#pragma unroll
        for (int j = 0; j < 4; j++) oacc[i][j] = 0.f;
    float lrow0 = 0.f, lrow1 = 0.f;   // lane-local partial sums

    for (int kt = 0; kt < S_LEN / 64; kt++) {
        CP_WAIT(1);
        __syncthreads();
        const h16* s  = dsm + AT_ST(kt & 1);
        const h16* sK = s;
        const h16* sV = s + AT_V;

        float sc[8][4];
#pragma unroll
        for (int i = 0; i < 8; i++)
#pragma unroll
            for (int j = 0; j < 4; j++) sc[i][j] = 0.f;

#pragma unroll
        for (int ks = 0; ks < 4; ks++) {
            uint32_t kb[4][4];
#pragma unroll
            for (int nh = 0; nh < 4; nh++) {
                const int krow = nh * 16 + (L & 7) + ((L >> 4) << 3);
                const int kcol = ks * 16 + (((L >> 3) & 1) << 3);
                ldsm4(smem_u32(sK + krow * TSTR + kcol), kb[nh][0], kb[nh][1], kb[nh][2], kb[nh][3]);
            }
#pragma unroll
            for (int nf = 0; nf < 8; nf++) {
                uint32_t b0 = kb[nf >> 1][(nf & 1) * 2], b1 = kb[nf >> 1][(nf & 1) * 2 + 1];
                mma16816(sc[nf], qf[ks][0], qf[ks][1], qf[ks][2], qf[ks][3], b0, b1);
            }
        }

        // skip-max softmax: p = exp2(s + mask*log2e), lane-local sums
        const float* mg = m2 + (size_t)b * S_LEN + kt * 64;
#pragma unroll
        for (int nf = 0; nf < 8; nf++) {
            const int c0 = nf * 8 + 2 * (L & 3);
            const float m0v = mg[c0], m1v = mg[c0 + 1];
            sc[nf][0] = fexp2(sc[nf][0] + m0v);
            sc[nf][1] = fexp2(sc[nf][1] + m1v);
            sc[nf][2] = fexp2(sc[nf][2] + m0v);
            sc[nf][3] = fexp2(sc[nf][3] + m1v);
            lrow0 += sc[nf][0] + sc[nf][1];
            lrow1 += sc[nf][2] + sc[nf][3];
        }

        // P @ V
#pragma unroll
        for (int ks = 0; ks < 4; ks++) {
            uint32_t a0 = fpack2(sc[2*ks][0],   sc[2*ks][1]);
            uint32_t a1 = fpack2(sc[2*ks][2],   sc[2*ks][3]);
            uint32_t a2 = fpack2(sc[2*ks+1][0], sc[2*ks+1][1]);
            uint32_t a3 = fpack2(sc[2*ks+1][2], sc[2*ks+1][3]);
            uint32_t vb[4][4];
#pragma unroll
            for (int dh = 0; dh < 4; dh++) {
                const int vrow = ks * 16 + (L & 15);
                const int vcol = dh * 16 + ((L >> 4) << 3);
                ldsm4t(smem_u32(sV + vrow * TSTR + vcol), vb[dh][0], vb[dh][1], vb[dh][2], vb[dh][3]);
            }
#pragma unroll
            for (int df = 0; df < 8; df++) {
                uint32_t b0 = vb[df >> 1][(df & 1) * 2], b1 = vb[df >> 1][(df & 1) * 2 + 1];
                mma16816(oacc[df], a0, a1, a2, a3, b0, b1);
            }
        }

        __syncthreads();
        if (kt + 2 < S_LEN / 64)
            attn_issue_kv(dsm, kh, vh, kt + 2, kt & 1, base, t);
        CP_COMMIT;
    }

    // one cross-lane reduction for l
    lrow0 += __shfl_xor_sync(0xffffffffu, lrow0, 1);
    lrow0 += __shfl_xor_sync(0xffffffffu, lrow0, 2);
    lrow1 += __shfl_xor_sync(0xffffffffu, lrow1, 1);
    lrow1 += __shfl_xor_sync(0xffffffffu, lrow1, 2);

    const float inv0 = 1.f / lrow0, inv1 = 1.f / lrow1;
    const int r0 = s0 + w * 16 + (L >> 2);
#pragma unroll
    for (int df = 0; df < 8; df++) {
        const int d = df * 8 + 2 * (L & 3);
        const size_t i0 = (size_t)r0 * ROWB + base + d;
        const size_t i1 = i0 + 8 * ROWB;
        *(uint32_t*)&ch_[i0] = fpack2(oacc[df][0] * inv0, oacc[df][1] * inv0);
        *(uint32_t*)&ch_[i1] = fpack2(oacc[df][2] * inv1, oacc[df][3] * inv1);
    }
}

// =================================================================
// LayerNorm (R7 version): block per row; emits fp32 + fp16
// =================================================================
__global__ __launch_bounds__(256)
void ln_kernel(const float* __restrict__ X, const float* __restrict__ gamma,
               const float* __restrict__ beta, float* __restrict__ out,
               h16* __restrict__ oh)
{
    const int row = blockIdx.x;
    const int t = threadIdx.x;
    const float* x = X + (size_t)row * HID;

    float4 v = *(const float4*)(x + t * 4);
    float s  = v.x + v.y + v.z + v.w;
    float sq = v.x*v.x + v.y*v.y + v.z*v.z + v.w*v.w;
#pragma unroll
    for (int off = 16; off; off >>= 1) {
        s  += __shfl_xor_sync(0xffffffffu, s,  off);
        sq += __shfl_xor_sync(0xffffffffu, sq, off);
    }
    __shared__ float ss[8], sqs[8];
    const int lane = t & 31, wid = t >> 5;
    if (lane == 0) { ss[wid] = s; sqs[wid] = sq; }
    __syncthreads();
    float tot = 0.f, totq = 0.f;
#pragma unroll
    for (int i = 0; i < 8; i++) { tot += ss[i]; totq += sqs[i]; }
    const float mean = tot * (1.f/1024.f);
    const float var  = totq * (1.f/1024.f) - mean * mean;
    const float rstd = rsqrtf(var + 1e-12f);

    float4 g  = *(const float4*)(gamma + t * 4);
    float4 bb = *(const float4*)(beta + t * 4);
    float4 o;
    o.x = (v.x - mean) * rstd * g.x + bb.x;
    o.y = (v.y - mean) * rstd * g.y + bb.y;
    o.z = (v.z - mean) * rstd * g.z + bb.z;
    o.w = (v.w - mean) * rstd * g.w + bb.w;
    *(float4*)(out + (size_t)row * HID + t * 4) = o;

    const size_t idx = (size_t)row * HID + t * 4;
    *(uint32_t*)&oh[idx]     = fpack2(o.x, o.y);
    *(uint32_t*)&oh[idx + 2] = fpack2(o.z, o.w);
}

// ---------------- conversion kernels ----------------
__global__ void wconv_kernel(const float* __restrict__ w0, const float* __restrict__ w1,
                             const float* __restrict__ w2, const float* __restrict__ w3,
                             h16* __restrict__ wdst)
{
    const float* src;
    const int m = blockIdx.y;
    if (m == 0) src = w0; else if (m == 1) src = w1; else if (m == 2) src = w2; else src = w3;
    const size_t off = (size_t)m * WELEM;
    for (size_t i = (size_t)blockIdx.x * blockDim.x + threadIdx.x; i < (size_t)WELEM;
         i += (size_t)gridDim.x * blockDim.x) {
        wdst[off + i] = __float2half_rn(src[i]);
    }
}

__global__ void xconv_kernel(const float* __restrict__ in, float* __restrict__ xo,
                             h16* __restrict__ xh,
                             const float* __restrict__ mask, float* __restrict__ m2)
{
    const size_t gid = (size_t)blockIdx.x * blockDim.x + threadIdx.x;
    if (gid < (size_t)BATCH * S_LEN)
        m2[gid] = mask[gid] * LOG2E;
    for (size_t i = gid; i < (size_t)NELEM;
         i += (size_t)gridDim.x * blockDim.x) {
        float v = in[i];
        xo[i] = v;
        xh[i] = __float2half_rn(v);
    }
}

// =================================================================
extern "C" void kernel_launch(void* const* d_in, const int* in_sizes, int n_in,
                              void* d_out, int out_size)
{
    const float* input = (const float*)d_in[0];
    const float* mask  = (const float*)d_in[1];
    const float* Wq = (const float*)d_in[2];
    const float* bq = (const float*)d_in[3];
    const float* Wk = (const float*)d_in[4];
    const float* bk = (const float*)d_in[5];
    const float* Wv = (const float*)d_in[6];
    const float* bv = (const float*)d_in[7];
    const float* Wo = (const float*)d_in[8];
    const float* bo = (const float*)d_in[9];
    const float* gamma = (const float*)d_in[10];
    const float* beta  = (const float*)d_in[11];

    float *x, *y, *m2; h16 *xh, *qh, *kh, *vh, *ch, *wv;
    cudaGetSymbolAddress((void**)&x,  g_x);  cudaGetSymbolAddress((void**)&y,  g_y);
    cudaGetSymbolAddress((void**)&m2, g_m2);
    cudaGetSymbolAddress((void**)&xh, g_xh);
    cudaGetSymbolAddress((void**)&qh, g_qh);
    cudaGetSymbolAddress((void**)&kh, g_kh); cudaGetSymbolAddress((void**)&vh, g_vh);
    cudaGetSymbolAddress((void**)&ch, g_ch);
    cudaGetSymbolAddress((void**)&wv, g_w);

    cudaFuncSetAttribute(attn_f16,     cudaFuncAttributeMaxDynamicSharedMemorySize, ATTN_SMEM);
    cudaFuncSetAttribute(qkv_kernel,   cudaFuncAttributeMaxDynamicSharedMemorySize, GEMM_SMEM);
    cudaFuncSetAttribute(oproj_kernel, cudaFuncAttributeMaxDynamicSharedMemorySize, GEMM_SMEM);

    wconv_kernel<<<dim3(4096, 4), 256>>>(Wq, Wk, Wv, Wo, wv);
    xconv_kernel<<<4096, 256>>>(input, x, xh, mask, m2);

    for (int l = 0; l < NLAYER; l++) {
        const size_t wq_o = (size_t)(0 * NLAYER + l) * HID * HID;
        const size_t wo_o = (size_t)(3 * NLAYER + l) * HID * HID;
        const size_t voff = (size_t)l * HID;

        qkv_kernel<<<dim3(8, 32, 3), 256, GEMM_SMEM>>>(
            xh, wv + wq_o,
            bq + voff, bk + voff, bv + voff,
            qh, kh, vh);

        attn_f16<<<dim3(S_LEN / QT, BATCH * NHEAD), 256, ATTN_SMEM>>>(
            qh, kh, vh, m2, ch);

        oproj_kernel<<<dim3(8, 32), 256, GEMM_SMEM>>>(ch, wv + wo_o,
                                                      bo + voff, x, y);

        float* dst = (l == NLAYER - 1) ? (float*)d_out : x;
        ln_kernel<<<M_ROWS, 256>>>(y, gamma + voff, beta + voff, dst, xh);
    }
}

// round 14
// speedup vs baseline: 1.0537x; 1.0537x over previous
#include <cuda_runtime.h>
#include <cuda_fp16.h>
#include <cstdint>

#define S_LEN  2048
#define BATCH  2
#define HID    1024
#define NHEAD  16
#define HDIM   64
#define NLAYER 12
#define M_ROWS (S_LEN*BATCH)   // 4096
#define ROWB   (BATCH*HID)     // 2048
#define NELEM  (M_ROWS*HID)
#define WELEM  (NLAYER*HID*HID)

typedef __half h16;

// ---------------- scratch ----------------
__device__ float g_x [NELEM];
__device__ float g_y [NELEM];
__device__ float g_m2[BATCH*S_LEN];        // mask * log2e
__device__ h16  g_xh[NELEM];
__device__ h16  g_qh[NELEM];
__device__ h16  g_kh[NELEM];
__device__ h16  g_vh[NELEM];
__device__ h16  g_ch[NELEM];
__device__ h16  g_w [4ull*WELEM];

// ---------------- helpers ----------------
__device__ __forceinline__ uint32_t smem_u32(const void* p) {
    return (uint32_t)__cvta_generic_to_shared(p);
}
__device__ __forceinline__ void cp16(void* s, const void* g) {
    asm volatile("cp.async.cg.shared.global [%0], [%1], 16;"
        :: "r"(smem_u32(s)), "l"(g));
}
#define CP_COMMIT asm volatile("cp.async.commit_group;")
#define CP_WAIT(N) asm volatile("cp.async.wait_group %0;" :: "n"(N))

__device__ __forceinline__ void ldsm4(uint32_t a, uint32_t& r0, uint32_t& r1, uint32_t& r2, uint32_t& r3) {
    asm volatile("ldmatrix.sync.aligned.m8n8.x4.shared.b16 {%0,%1,%2,%3},[%4];"
        : "=r"(r0), "=r"(r1), "=r"(r2), "=r"(r3) : "r"(a));
}
__device__ __forceinline__ void ldsm4t(uint32_t a, uint32_t& r0, uint32_t& r1, uint32_t& r2, uint32_t& r3) {
    asm volatile("ldmatrix.sync.aligned.m8n8.x4.trans.shared.b16 {%0,%1,%2,%3},[%4];"
        : "=r"(r0), "=r"(r1), "=r"(r2), "=r"(r3) : "r"(a));
}
__device__ __forceinline__ void mma16816(float* c, uint32_t a0, uint32_t a1, uint32_t a2, uint32_t a3,
                                         uint32_t b0, uint32_t b1) {
    asm volatile("mma.sync.aligned.m16n8k16.row.col.f32.f16.f16.f32 "
        "{%0,%1,%2,%3},{%4,%5,%6,%7},{%8,%9},{%0,%1,%2,%3};"
        : "+f"(c[0]), "+f"(c[1]), "+f"(c[2]), "+f"(c[3])
        : "r"(a0), "r"(a1), "r"(a2), "r"(a3), "r"(b0), "r"(b1));
}
__device__ __forceinline__ float fexp2(float x) {
    float r;
    asm("ex2.approx.ftz.f32 %0, %1;" : "=f"(r) : "f"(x));
    return r;
}
__device__ __forceinline__ uint32_t fpack2(float x, float y) {
    __half2 p = __floats2half2_rn(x, y);
    return *reinterpret_cast<uint32_t*>(&p);
}

#define LOG2E 1.4426950408889634f
#define SCL2  (0.125f * LOG2E)

// =================================================================
// fp16 GEMM, cp.async double-buffered (exact R11).
// block 128x128, 256 thr = 8 warps (2m x 4n), warp 64x32, KT=32
// =================================================================
#define ASTR 56
#define BSTR 136
#define SA_OFF(st) ((st)*128*ASTR)
#define SB_BASE (2*128*ASTR)
#define SB_OFF(st) (SB_BASE + (st)*32*BSTR)
#define GEMM_SMEM ((2*128*ASTR + 2*32*BSTR)*(int)sizeof(h16))  // 46080

__device__ __forceinline__ void gemm_issue(
    h16* dsm, const h16* __restrict__ A, const h16* __restrict__ W,
    int m0, int n0, int k0, int st, int t)
{
    const int ar = t >> 1, ac = (t & 1) * 16;
    const size_t ga = (size_t)(m0 + ar) * HID + k0 + ac;
    h16* a0 = dsm + SA_OFF(st) + ar * ASTR + ac;
    cp16(a0, A + ga); cp16(a0 + 8, A + ga + 8);
    const int br = t >> 3, bc = (t & 7) * 16;
    const size_t gb = (size_t)(k0 + br) * HID + n0 + bc;
    h16* b0 = dsm + SB_OFF(st) + br * BSTR + bc;
    cp16(b0, W + gb); cp16(b0 + 8, W + gb + 8);
}

__device__ __forceinline__ void gemm_core(
    const h16* __restrict__ A, const h16* __restrict__ W, float acc[4][4][4])
{
    extern __shared__ h16 dsm[];
    const int t = threadIdx.x;
    const int L = t & 31, w = t >> 5;
    const int wm = (w >> 2) * 64, wn = (w & 3) * 32;
    const int m0 = blockIdx.y * 128, n0 = blockIdx.x * 128;

#pragma unroll
    for (int i = 0; i < 4; i++)
#pragma unroll
        for (int j = 0; j < 4; j++)
#pragma unroll
            for (int r = 0; r < 4; r++) acc[i][j][r] = 0.f;

    gemm_issue(dsm, A, W, m0, n0, 0,  0, t); CP_COMMIT;
    gemm_issue(dsm, A, W, m0, n0, 32, 1, t); CP_COMMIT;

    for (int ko = 0; ko < HID / 32; ko++) {
        CP_WAIT(1);
        __syncthreads();
        const int st = ko & 1;
        const h16* cA = dsm + SA_OFF(st);
        const h16* cB = dsm + SB_OFF(st);
#pragma unroll
        for (int ks = 0; ks < 2; ks++) {
            const int kk = ks * 16;
            uint32_t bb[2][4];
#pragma unroll
            for (int nh = 0; nh < 2; nh++) {
                const int brow = kk + (L & 15);
                const int bcol = wn + nh * 16 + ((L >> 4) << 3);
                ldsm4t(smem_u32(cB + brow * BSTR + bcol), bb[nh][0], bb[nh][1], bb[nh][2], bb[nh][3]);
            }
#pragma unroll
            for (int mf = 0; mf < 4; mf++) {
                const int arow = wm + mf * 16 + (L & 15);
                const int acol = kk + ((L >> 4) << 3);
                uint32_t a0, a1, a2, a3;
                ldsm4(smem_u32(cA + arow * ASTR + acol), a0, a1, a2, a3);
#pragma unroll
                for (int nf = 0; nf < 4; nf++) {
                    uint32_t b0 = bb[nf >> 1][(nf & 1) * 2], b1 = bb[nf >> 1][(nf & 1) * 2 + 1];
                    mma16816(acc[mf][nf], a0, a1, a2, a3, b0, b1);
                }
            }
        }
        __syncthreads();
        if (ko + 2 < HID / 32)
            gemm_issue(dsm, A, W, m0, n0, (ko + 2) * 32, st, t);
        CP_COMMIT;
    }
}

// z=0: Q output, scaled by SCL2. z=1: K. z=2: V.
__global__ __launch_bounds__(256, 2)
void qkv_kernel(const h16* __restrict__ xh,
                const h16* __restrict__ wbase,
                const float* __restrict__ bq, const float* __restrict__ bk, const float* __restrict__ bv,
                h16* __restrict__ qh, h16* __restrict__ kh, h16* __restrict__ vh)
{
    const int z = blockIdx.z;
    const h16* W = wbase + (size_t)z * NLAYER * HID * HID;
    const float* bias = (z == 0) ? bq : (z == 1) ? bk : bv;
    h16* out = (z == 0) ? qh : (z == 1) ? kh : vh;
    const float scl = (z == 0) ? SCL2 : 1.0f;

    float acc[4][4][4];
    gemm_core(xh, W, acc);

    const int t = threadIdx.x, L = t & 31, w = t >> 5;
    const int wm = (w >> 2) * 64, wn = (w & 3) * 32;
    const int m0 = blockIdx.y * 128, n0 = blockIdx.x * 128;
#pragma unroll
    for (int mf = 0; mf < 4; mf++) {
        const int r0 = m0 + wm + mf * 16 + (L >> 2);
#pragma unroll
        for (int nf = 0; nf < 4; nf++) {
            const int c = n0 + wn + nf * 8 + 2 * (L & 3);
            const float b0 = bias[c], b1 = bias[c + 1];
            *(uint32_t*)&out[(size_t)r0 * HID + c] =
                fpack2((acc[mf][nf][0] + b0) * scl, (acc[mf][nf][1] + b1) * scl);
            *(uint32_t*)&out[(size_t)(r0 + 8) * HID + c] =
                fpack2((acc[mf][nf][2] + b0) * scl, (acc[mf][nf][3] + b1) * scl);
        }
    }
}

__global__ __launch_bounds__(256, 2)
void oproj_kernel(const h16* __restrict__ ch_, const h16* __restrict__ W,
                  const float* __restrict__ bias, const float* __restrict__ res,
                  float* __restrict__ y)
{
    float acc[4][4][4];
    gemm_core(ch_, W, acc);

    const int t = threadIdx.x, L = t & 31, w = t >> 5;
    const int wm = (w >> 2) * 64, wn = (w & 3) * 32;
    const int m0 = blockIdx.y * 128, n0 = blockIdx.x * 128;
#pragma unroll
    for (int mf = 0; mf < 4; mf++) {
        const int r0 = m0 + wm + mf * 16 + (L >> 2);
#pragma unroll
        for (int nf = 0; nf < 4; nf++) {
            const int c = n0 + wn + nf * 8 + 2 * (L & 3);
            const float b0 = bias[c], b1 = bias[c + 1];
            float2 rv0 = *(const float2*)&res[(size_t)r0 * HID + c];
            float2 rv1 = *(const float2*)&res[(size_t)(r0 + 8) * HID + c];
            float2 o0 = { acc[mf][nf][0] + b0 + rv0.x, acc[mf][nf][1] + b1 + rv0.y };
            float2 o1 = { acc[mf][nf][2] + b0 + rv1.x, acc[mf][nf][3] + b1 + rv1.y };
            *(float2*)&y[(size_t)r0 * HID + c]       = o0;
            *(float2*)&y[(size_t)(r0 + 8) * HID + c] = o1;
        }
    }
}

// =================================================================
// Flash attention fp16 (EXACT R11): 256 thr (8 warps), 16 Q rows/warp,
// QT=128, K-tile 64, 2-stage cp.async KV pipeline, skip-max softmax.
// =================================================================
#define TSTR 72
#define QT   128
#define AT_Q  0
#define AT_ST(st) (QT*TSTR + (st)*2*64*TSTR)
#define AT_V  (64*TSTR)
#define ATTN_SMEM ((QT*TSTR + 4*64*TSTR)*(int)sizeof(h16))  // 55296

__device__ __forceinline__ void attn_issue_kv(
    h16* dsm, const h16* __restrict__ kh, const h16* __restrict__ vh,
    int kt, int st, int base, int t)
{
    const int row = t >> 2, c4 = (t & 3) * 16;
    const size_t g = (size_t)(kt * 64 + row) * ROWB + base + c4;
    h16* s = dsm + AT_ST(st);
    h16* pk = s +        row * TSTR + c4;
    h16* pv = s + AT_V + row * TSTR + c4;
    cp16(pk, kh + g); cp16(pk + 8, kh + g + 8);
    cp16(pv, vh + g); cp16(pv + 8, vh + g + 8);
}

__global__ __launch_bounds__(256, 2)
void attn_f16(const h16* __restrict__ qh,
              const h16* __restrict__ kh, const h16* __restrict__ vh,
              const float* __restrict__ m2,
              h16* __restrict__ ch_)
{
    extern __shared__ h16 dsm[];
    const int t = threadIdx.x, L = t & 31, w = t >> 5;
    const int s0 = blockIdx.x * QT;
    const int b  = blockIdx.y >> 4, h = blockIdx.y & 15;
    const int base = b * HID + h * HDIM;

    {
        const int row = t >> 1, cc = (t & 1) * 32;
        const size_t g = (size_t)(s0 + row) * ROWB + base + cc;
        h16* pq = dsm + AT_Q + row * TSTR + cc;
#pragma unroll
        for (int c = 0; c < 4; c++)
            cp16(pq + c * 8, qh + g + c * 8);
    }
    CP_COMMIT;
    attn_issue_kv(dsm, kh, vh, 0, 0, base, t); CP_COMMIT;
    attn_issue_kv(dsm, kh, vh, 1, 1, base, t); CP_COMMIT;

    CP_WAIT(2);
    __syncthreads();

    uint32_t qf[4][4];
#pragma unroll
    for (int ks = 0; ks < 4; ks++) {
        const int qrow = w * 16 + (L & 15);
        const int qcol = ks * 16 + ((L >> 4) << 3);
        ldsm4(smem_u32(dsm + AT_Q + qrow * TSTR + qcol), qf[ks][0], qf[ks][1], qf[ks][2], qf[ks][3]);
    }

    float oacc[8][4];
#pragma unroll
    for (int i = 0; i < 8; i++)
#pragma unroll
        for (int j = 0; j < 4; j++) oacc[i][j] = 0.f;
    float lrow0 = 0.f, lrow1 = 0.f;   // lane-local partial sums

    for (int kt = 0; kt < S_LEN / 64; kt++) {
        CP_WAIT(1);
        __syncthreads();
        const h16* s  = dsm + AT_ST(kt & 1);
        const h16* sK = s;
        const h16* sV = s + AT_V;

        float sc[8][4];
#pragma unroll
        for (int i = 0; i < 8; i++)
#pragma unroll
            for (int j = 0; j < 4; j++) sc[i][j] = 0.f;

#pragma unroll
        for (int ks = 0; ks < 4; ks++) {
            uint32_t kb[4][4];
#pragma unroll
            for (int nh = 0; nh < 4; nh++) {
                const int krow = nh * 16 + (L & 7) + ((L >> 4) << 3);
                const int kcol = ks * 16 + (((L >> 3) & 1) << 3);
                ldsm4(smem_u32(sK + krow * TSTR + kcol), kb[nh][0], kb[nh][1], kb[nh][2], kb[nh][3]);
            }
#pragma unroll
            for (int nf = 0; nf < 8; nf++) {
                uint32_t b0 = kb[nf >> 1][(nf & 1) * 2], b1 = kb[nf >> 1][(nf & 1) * 2 + 1];
                mma16816(sc[nf], qf[ks][0], qf[ks][1], qf[ks][2], qf[ks][3], b0, b1);
            }
        }

        // skip-max softmax: p = exp2(s + mask*log2e), lane-local sums
        const float* mg = m2 + (size_t)b * S_LEN + kt * 64;
#pragma unroll
        for (int nf = 0; nf < 8; nf++) {
            const int c0 = nf * 8 + 2 * (L & 3);
            const float m0v = mg[c0], m1v = mg[c0 + 1];
            sc[nf][0] = fexp2(sc[nf][0] + m0v);
            sc[nf][1] = fexp2(sc[nf][1] + m1v);
            sc[nf][2] = fexp2(sc[nf][2] + m0v);
            sc[nf][3] = fexp2(sc[nf][3] + m1v);
            lrow0 += sc[nf][0] + sc[nf][1];
            lrow1 += sc[nf][2] + sc[nf][3];
        }

        // P @ V
#pragma unroll
        for (int ks = 0; ks < 4; ks++) {
            uint32_t a0 = fpack2(sc[2*ks][0],   sc[2*ks][1]);
            uint32_t a1 = fpack2(sc[2*ks][2],   sc[2*ks][3]);
            uint32_t a2 = fpack2(sc[2*ks+1][0], sc[2*ks+1][1]);
            uint32_t a3 = fpack2(sc[2*ks+1][2], sc[2*ks+1][3]);
            uint32_t vb[4][4];
#pragma unroll
            for (int dh = 0; dh < 4; dh++) {
                const int vrow = ks * 16 + (L & 15);
                const int vcol = dh * 16 + ((L >> 4) << 3);
                ldsm4t(smem_u32(sV + vrow * TSTR + vcol), vb[dh][0], vb[dh][1], vb[dh][2], vb[dh][3]);
            }
#pragma unroll
            for (int df = 0; df < 8; df++) {
                uint32_t b0 = vb[df >> 1][(df & 1) * 2], b1 = vb[df >> 1][(df & 1) * 2 + 1];
                mma16816(oacc[df], a0, a1, a2, a3, b0, b1);
            }
        }

        __syncthreads();
        if (kt + 2 < S_LEN / 64)
            attn_issue_kv(dsm, kh, vh, kt + 2, kt & 1, base, t);
        CP_COMMIT;
    }

    // one cross-lane reduction for l
    lrow0 += __shfl_xor_sync(0xffffffffu, lrow0, 1);
    lrow0 += __shfl_xor_sync(0xffffffffu, lrow0, 2);
    lrow1 += __shfl_xor_sync(0xffffffffu, lrow1, 1);
    lrow1 += __shfl_xor_sync(0xffffffffu, lrow1, 2);

    const float inv0 = 1.f / lrow0, inv1 = 1.f / lrow1;
    const int r0 = s0 + w * 16 + (L >> 2);
#pragma unroll
    for (int df = 0; df < 8; df++) {
        const int d = df * 8 + 2 * (L & 3);
        const size_t i0 = (size_t)r0 * ROWB + base + d;
        const size_t i1 = i0 + 8 * ROWB;
        *(uint32_t*)&ch_[i0] = fpack2(oacc[df][0] * inv0, oacc[df][1] * inv0);
        *(uint32_t*)&ch_[i1] = fpack2(oacc[df][2] * inv1, oacc[df][3] * inv1);
    }
}

// =================================================================
// LayerNorm: warp per row, 8 rows per block; emits fp32 + fp16
// =================================================================
__global__ __launch_bounds__(256)
void ln_kernel(const float* __restrict__ X, const float* __restrict__ gamma,
               const float* __restrict__ beta, float* __restrict__ out,
               h16* __restrict__ oh)
{
    const int lane = threadIdx.x & 31, wid = threadIdx.x >> 5;
    const int row  = blockIdx.x * 8 + wid;
    const float* x = X + (size_t)row * HID + lane * 32;

    float4 v[8];
    float s = 0.f, sq = 0.f;
#pragma unroll
    for (int i = 0; i < 8; i++) {
        v[i] = *(const float4*)(x + i * 4);
        s  += v[i].x + v[i].y + v[i].z + v[i].w;
        sq += v[i].x*v[i].x + v[i].y*v[i].y + v[i].z*v[i].z + v[i].w*v[i].w;
    }
#pragma unroll
    for (int off = 16; off; off >>= 1) {
        s  += __shfl_xor_sync(0xffffffffu, s,  off);
        sq += __shfl_xor_sync(0xffffffffu, sq, off);
    }
    const float mean = s * (1.f/1024.f);
    const float var  = sq * (1.f/1024.f) - mean * mean;
    const float rstd = rsqrtf(var + 1e-12f);

    const float* gp = gamma + lane * 32;
    const float* bp = beta  + lane * 32;
    float* op = out + (size_t)row * HID + lane * 32;
    h16*  hp = oh  + (size_t)row * HID + lane * 32;
#pragma unroll
    for (int i = 0; i < 8; i++) {
        float4 g  = *(const float4*)(gp + i * 4);
        float4 bb = *(const float4*)(bp + i * 4);
        float4 o;
        o.x = (v[i].x - mean) * rstd * g.x + bb.x;
        o.y = (v[i].y - mean) * rstd * g.y + bb.y;
        o.z = (v[i].z - mean) * rstd * g.z + bb.z;
        o.w = (v[i].w - mean) * rstd * g.w + bb.w;
        *(float4*)(op + i * 4) = o;
        *(uint32_t*)(hp + i * 4)     = fpack2(o.x, o.y);
        *(uint32_t*)(hp + i * 4 + 2) = fpack2(o.z, o.w);
    }
}

// ---------------- conversion kernels ----------------
__global__ void wconv_kernel(const float* __restrict__ w0, const float* __restrict__ w1,
                             const float* __restrict__ w2, const float* __restrict__ w3,
                             h16* __restrict__ wdst)
{
    const float* src;
    const int m = blockIdx.y;
    if (m == 0) src = w0; else if (m == 1) src = w1; else if (m == 2) src = w2; else src = w3;
    const size_t off = (size_t)m * WELEM;
    for (size_t i = (size_t)blockIdx.x * blockDim.x + threadIdx.x; i < (size_t)WELEM;
         i += (size_t)gridDim.x * blockDim.x) {
        wdst[off + i] = __float2half_rn(src[i]);
    }
}

__global__ void xconv_kernel(const float* __restrict__ in, float* __restrict__ xo,
                             h16* __restrict__ xh,
                             const float* __restrict__ mask, float* __restrict__ m2)
{
    const size_t gid = (size_t)blockIdx.x * blockDim.x + threadIdx.x;
    if (gid < (size_t)BATCH * S_LEN)
        m2[gid] = mask[gid] * LOG2E;
    for (size_t i = gid; i < (size_t)NELEM;
         i += (size_t)gridDim.x * blockDim.x) {
        float v = in[i];
        xo[i] = v;
        xh[i] = __float2half_rn(v);
    }
}

// =================================================================
extern "C" void kernel_launch(void* const* d_in, const int* in_sizes, int n_in,
                              void* d_out, int out_size)
{
    const float* input = (const float*)d_in[0];
    const float* mask  = (const float*)d_in[1];
    const float* Wq = (const float*)d_in[2];
    const float* bq = (const float*)d_in[3];
    const float* Wk = (const float*)d_in[4];
    const float* bk = (const float*)d_in[5];
    const float* Wv = (const float*)d_in[6];
    const float* bv = (const float*)d_in[7];
    const float* Wo = (const float*)d_in[8];
    const float* bo = (const float*)d_in[9];
    const float* gamma = (const float*)d_in[10];
    const float* beta  = (const float*)d_in[11];

    float *x, *y, *m2; h16 *xh, *qh, *kh, *vh, *ch, *wv;
    cudaGetSymbolAddress((void**)&x,  g_x);  cudaGetSymbolAddress((void**)&y,  g_y);
    cudaGetSymbolAddress((void**)&m2, g_m2);
    cudaGetSymbolAddress((void**)&xh, g_xh);
    cudaGetSymbolAddress((void**)&qh, g_qh);
    cudaGetSymbolAddress((void**)&kh, g_kh); cudaGetSymbolAddress((void**)&vh, g_vh);
    cudaGetSymbolAddress((void**)&ch, g_ch);
    cudaGetSymbolAddress((void**)&wv, g_w);

    cudaFuncSetAttribute(attn_f16,     cudaFuncAttributeMaxDynamicSharedMemorySize, ATTN_SMEM);
    cudaFuncSetAttribute(qkv_kernel,   cudaFuncAttributeMaxDynamicSharedMemorySize, GEMM_SMEM);
    cudaFuncSetAttribute(oproj_kernel, cudaFuncAttributeMaxDynamicSharedMemorySize, GEMM_SMEM);

    wconv_kernel<<<dim3(4096, 4), 256>>>(Wq, Wk, Wv, Wo, wv);
    xconv_kernel<<<4096, 256>>>(input, x, xh, mask, m2);

    for (int l = 0; l < NLAYER; l++) {
        const size_t wq_o = (size_t)(0 * NLAYER + l) * HID * HID;
        const size_t wo_o = (size_t)(3 * NLAYER + l) * HID * HID;
        const size_t voff = (size_t)l * HID;

        qkv_kernel<<<dim3(8, 32, 3), 256, GEMM_SMEM>>>(
            xh, wv + wq_o,
            bq + voff, bk + voff, bv + voff,
            qh, kh, vh);

        attn_f16<<<dim3(S_LEN / QT, BATCH * NHEAD), 256, ATTN_SMEM>>>(
            qh, kh, vh, m2, ch);

        oproj_kernel<<<dim3(8, 32), 256, GEMM_SMEM>>>(ch, wv + wo_o,
                                                      bo + voff, x, y);

        float* dst = (l == NLAYER - 1) ? (float*)d_out : x;
        ln_kernel<<<M_ROWS / 8, 256>>>(y, gamma + voff, beta + voff, dst, xh);
    }
}

// round 15
// speedup vs baseline: 1.1299x; 1.0723x over previous
#include <cuda_runtime.h>
#include <cuda_fp16.h>
#include <cstdint>

#define S_LEN  2048
#define BATCH  2
#define HID    1024
#define NHEAD  16
#define HDIM   64
#define NLAYER 12
#define M_ROWS (S_LEN*BATCH)   // 4096
#define ROWB   (BATCH*HID)     // 2048
#define NELEM  (M_ROWS*HID)
#define WELEM  (NLAYER*HID*HID)

typedef __half h16;

// ---------------- scratch ----------------
__device__ float g_x [NELEM];
__device__ float g_y [NELEM];
__device__ float g_m2[BATCH*S_LEN];        // mask * log2e
__device__ h16  g_xh[NELEM];
__device__ h16  g_qh[NELEM];
__device__ h16  g_kh[NELEM];
__device__ h16  g_vh[NELEM];
__device__ h16  g_ch[NELEM];
__device__ h16  g_w [4ull*WELEM];

// ---------------- helpers ----------------
__device__ __forceinline__ uint32_t smem_u32(const void* p) {
    return (uint32_t)__cvta_generic_to_shared(p);
}
__device__ __forceinline__ void cp16(void* s, const void* g) {
    asm volatile("cp.async.cg.shared.global [%0], [%1], 16;"
        :: "r"(smem_u32(s)), "l"(g));
}
#define CP_COMMIT asm volatile("cp.async.commit_group;")
#define CP_WAIT(N) asm volatile("cp.async.wait_group %0;" :: "n"(N))

__device__ __forceinline__ void ldsm4(uint32_t a, uint32_t& r0, uint32_t& r1, uint32_t& r2, uint32_t& r3) {
    asm volatile("ldmatrix.sync.aligned.m8n8.x4.shared.b16 {%0,%1,%2,%3},[%4];"
        : "=r"(r0), "=r"(r1), "=r"(r2), "=r"(r3) : "r"(a));
}
__device__ __forceinline__ void ldsm4t(uint32_t a, uint32_t& r0, uint32_t& r1, uint32_t& r2, uint32_t& r3) {
    asm volatile("ldmatrix.sync.aligned.m8n8.x4.trans.shared.b16 {%0,%1,%2,%3},[%4];"
        : "=r"(r0), "=r"(r1), "=r"(r2), "=r"(r3) : "r"(a));
}
__device__ __forceinline__ void mma16816(float* c, uint32_t a0, uint32_t a1, uint32_t a2, uint32_t a3,
                                         uint32_t b0, uint32_t b1) {
    asm volatile("mma.sync.aligned.m16n8k16.row.col.f32.f16.f16.f32 "
        "{%0,%1,%2,%3},{%4,%5,%6,%7},{%8,%9},{%0,%1,%2,%3};"
        : "+f"(c[0]), "+f"(c[1]), "+f"(c[2]), "+f"(c[3])
        : "r"(a0), "r"(a1), "r"(a2), "r"(a3), "r"(b0), "r"(b1));
}
__device__ __forceinline__ float fexp2(float x) {
    float r;
    asm("ex2.approx.ftz.f32 %0, %1;" : "=f"(r) : "f"(x));
    return r;
}
__device__ __forceinline__ uint32_t fpack2(float x, float y) {
    __half2 p = __floats2half2_rn(x, y);
    return *reinterpret_cast<uint32_t*>(&p);
}

#define LOG2E 1.4426950408889634f
#define SCL2  (0.125f * LOG2E)

// =================================================================
// fp16 GEMM, cp.async double-buffered (exact R11).
// block 128x128, 256 thr = 8 warps (2m x 4n), warp 64x32, KT=32
// =================================================================
#define ASTR 56
#define BSTR 136
#define SA_OFF(st) ((st)*128*ASTR)
#define SB_BASE (2*128*ASTR)
#define SB_OFF(st) (SB_BASE + (st)*32*BSTR)
#define GEMM_SMEM ((2*128*ASTR + 2*32*BSTR)*(int)sizeof(h16))  // 46080

__device__ __forceinline__ void gemm_issue(
    h16* dsm, const h16* __restrict__ A, const h16* __restrict__ W,
    int m0, int n0, int k0, int st, int t)
{
    const int ar = t >> 1, ac = (t & 1) * 16;
    const size_t ga = (size_t)(m0 + ar) * HID + k0 + ac;
    h16* a0 = dsm + SA_OFF(st) + ar * ASTR + ac;
    cp16(a0, A + ga); cp16(a0 + 8, A + ga + 8);
    const int br = t >> 3, bc = (t & 7) * 16;
    const size_t gb = (size_t)(k0 + br) * HID + n0 + bc;
    h16* b0 = dsm + SB_OFF(st) + br * BSTR + bc;
    cp16(b0, W + gb); cp16(b0 + 8, W + gb + 8);
}

__device__ __forceinline__ void gemm_core(
    const h16* __restrict__ A, const h16* __restrict__ W, float acc[4][4][4])
{
    extern __shared__ h16 dsm[];
    const int t = threadIdx.x;
    const int L = t & 31, w = t >> 5;
    const int wm = (w >> 2) * 64, wn = (w & 3) * 32;
    const int m0 = blockIdx.y * 128, n0 = blockIdx.x * 128;

#pragma unroll
    for (int i = 0; i < 4; i++)
#pragma unroll
        for (int j = 0; j < 4; j++)
#pragma unroll
            for (int r = 0; r < 4; r++) acc[i][j][r] = 0.f;

    gemm_issue(dsm, A, W, m0, n0, 0,  0, t); CP_COMMIT;
    gemm_issue(dsm, A, W, m0, n0, 32, 1, t); CP_COMMIT;

    for (int ko = 0; ko < HID / 32; ko++) {
        CP_WAIT(1);
        __syncthreads();
        const int st = ko & 1;
        const h16* cA = dsm + SA_OFF(st);
        const h16* cB = dsm + SB_OFF(st);
#pragma unroll
        for (int ks = 0; ks < 2; ks++) {
            const int kk = ks * 16;
            uint32_t bb[2][4];
#pragma unroll
            for (int nh = 0; nh < 2; nh++) {
                const int brow = kk + (L & 15);
                const int bcol = wn + nh * 16 + ((L >> 4) << 3);
                ldsm4t(smem_u32(cB + brow * BSTR + bcol), bb[nh][0], bb[nh][1], bb[nh][2], bb[nh][3]);
            }
#pragma unroll
            for (int mf = 0; mf < 4; mf++) {
                const int arow = wm + mf * 16 + (L & 15);
                const int acol = kk + ((L >> 4) << 3);
                uint32_t a0, a1, a2, a3;
                ldsm4(smem_u32(cA + arow * ASTR + acol), a0, a1, a2, a3);
#pragma unroll
                for (int nf = 0; nf < 4; nf++) {
                    uint32_t b0 = bb[nf >> 1][(nf & 1) * 2], b1 = bb[nf >> 1][(nf & 1) * 2 + 1];
                    mma16816(acc[mf][nf], a0, a1, a2, a3, b0, b1);
                }
            }
        }
        __syncthreads();
        if (ko + 2 < HID / 32)
            gemm_issue(dsm, A, W, m0, n0, (ko + 2) * 32, st, t);
        CP_COMMIT;
    }
}

// z=0: Q output, scaled by SCL2. z=1: K. z=2: V.
__global__ __launch_bounds__(256, 2)
void qkv_kernel(const h16* __restrict__ xh,
                const h16* __restrict__ wbase,
                const float* __restrict__ bq, const float* __restrict__ bk, const float* __restrict__ bv,
                h16* __restrict__ qh, h16* __restrict__ kh, h16* __restrict__ vh)
{
    const int z = blockIdx.z;
    const h16* W = wbase + (size_t)z * NLAYER * HID * HID;
    const float* bias = (z == 0) ? bq : (z == 1) ? bk : bv;
    h16* out = (z == 0) ? qh : (z == 1) ? kh : vh;
    const float scl = (z == 0) ? SCL2 : 1.0f;

    float acc[4][4][4];
    gemm_core(xh, W, acc);

    const int t = threadIdx.x, L = t & 31, w = t >> 5;
    const int wm = (w >> 2) * 64, wn = (w & 3) * 32;
    const int m0 = blockIdx.y * 128, n0 = blockIdx.x * 128;
#pragma unroll
    for (int mf = 0; mf < 4; mf++) {
        const int r0 = m0 + wm + mf * 16 + (L >> 2);
#pragma unroll
        for (int nf = 0; nf < 4; nf++) {
            const int c = n0 + wn + nf * 8 + 2 * (L & 3);
            const float b0 = bias[c], b1 = bias[c + 1];
            *(uint32_t*)&out[(size_t)r0 * HID + c] =
                fpack2((acc[mf][nf][0] + b0) * scl, (acc[mf][nf][1] + b1) * scl);
            *(uint32_t*)&out[(size_t)(r0 + 8) * HID + c] =
                fpack2((acc[mf][nf][2] + b0) * scl, (acc[mf][nf][3] + b1) * scl);
        }
    }
}

__global__ __launch_bounds__(256, 2)
void oproj_kernel(const h16* __restrict__ ch_, const h16* __restrict__ W,
                  const float* __restrict__ bias, const float* __restrict__ res,
                  float* __restrict__ y)
{
    float acc[4][4][4];
    gemm_core(ch_, W, acc);

    const int t = threadIdx.x, L = t & 31, w = t >> 5;
    const int wm = (w >> 2) * 64, wn = (w & 3) * 32;
    const int m0 = blockIdx.y * 128, n0 = blockIdx.x * 128;
#pragma unroll
    for (int mf = 0; mf < 4; mf++) {
        const int r0 = m0 + wm + mf * 16 + (L >> 2);
#pragma unroll
        for (int nf = 0; nf < 4; nf++) {
            const int c = n0 + wn + nf * 8 + 2 * (L & 3);
            const float b0 = bias[c], b1 = bias[c + 1];
            float2 rv0 = *(const float2*)&res[(size_t)r0 * HID + c];
            float2 rv1 = *(const float2*)&res[(size_t)(r0 + 8) * HID + c];
            float2 o0 = { acc[mf][nf][0] + b0 + rv0.x, acc[mf][nf][1] + b1 + rv0.y };
            float2 o1 = { acc[mf][nf][2] + b0 + rv1.x, acc[mf][nf][3] + b1 + rv1.y };
            *(float2*)&y[(size_t)r0 * HID + c]       = o0;
            *(float2*)&y[(size_t)(r0 + 8) * HID + c] = o1;
        }
    }
}

// =================================================================
// Flash attention fp16 (EXACT R11): 256 thr (8 warps), 16 Q rows/warp,
// QT=128, K-tile 64, 2-stage cp.async KV pipeline, skip-max softmax.
// =================================================================
#define TSTR 72
#define QT   128
#define AT_Q  0
#define AT_ST(st) (QT*TSTR + (st)*2*64*TSTR)
#define AT_V  (64*TSTR)
#define ATTN_SMEM ((QT*TSTR + 4*64*TSTR)*(int)sizeof(h16))  // 55296

__device__ __forceinline__ void attn_issue_kv(
    h16* dsm, const h16* __restrict__ kh, const h16* __restrict__ vh,
    int kt, int st, int base, int t)
{
    const int row = t >> 2, c4 = (t & 3) * 16;
    const size_t g = (size_t)(kt * 64 + row) * ROWB + base + c4;
    h16* s = dsm + AT_ST(st);
    h16* pk = s +        row * TSTR + c4;
    h16* pv = s + AT_V + row * TSTR + c4;
    cp16(pk, kh + g); cp16(pk + 8, kh + g + 8);
    cp16(pv, vh + g); cp16(pv + 8, vh + g + 8);
}

__global__ __launch_bounds__(256, 2)
void attn_f16(const h16* __restrict__ qh,
              const h16* __restrict__ kh, const h16* __restrict__ vh,
              const float* __restrict__ m2,
              h16* __restrict__ ch_)
{
    extern __shared__ h16 dsm[];
    const int t = threadIdx.x, L = t & 31, w = t >> 5;
    const int s0 = blockIdx.x * QT;
    const int b  = blockIdx.y >> 4, h = blockIdx.y & 15;
    const int base = b * HID + h * HDIM;

    {
        const int row = t >> 1, cc = (t & 1) * 32;
        const size_t g = (size_t)(s0 + row) * ROWB + base + cc;
        h16* pq = dsm + AT_Q + row * TSTR + cc;
#pragma unroll
        for (int c = 0; c < 4; c++)
            cp16(pq + c * 8, qh + g + c * 8);
    }
    CP_COMMIT;
    attn_issue_kv(dsm, kh, vh, 0, 0, base, t); CP_COMMIT;
    attn_issue_kv(dsm, kh, vh, 1, 1, base, t); CP_COMMIT;

    CP_WAIT(2);
    __syncthreads();

    uint32_t qf[4][4];
#pragma unroll
    for (int ks = 0; ks < 4; ks++) {
        const int qrow = w * 16 + (L & 15);
        const int qcol = ks * 16 + ((L >> 4) << 3);
        ldsm4(smem_u32(dsm + AT_Q + qrow * TSTR + qcol), qf[ks][0], qf[ks][1], qf[ks][2], qf[ks][3]);
    }

    float oacc[8][4];
#pragma unroll
    for (int i = 0; i < 8; i++)
#pragma unroll
        for (int j = 0; j < 4; j++) oacc[i][j] = 0.f;
    float lrow0 = 0.f, lrow1 = 0.f;   // lane-local partial sums

    for (int kt = 0; kt < S_LEN / 64; kt++) {
        CP_WAIT(1);
        __syncthreads();
        const h16* s  = dsm + AT_ST(kt & 1);
        const h16* sK = s;
        const h16* sV = s + AT_V;

        float sc[8][4];
#pragma unroll
        for (int i = 0; i < 8; i++)
#pragma unroll
            for (int j = 0; j < 4; j++) sc[i][j] = 0.f;

#pragma unroll
        for (int ks = 0; ks < 4; ks++) {
            uint32_t kb[4][4];
#pragma unroll
            for (int nh = 0; nh < 4; nh++) {
                const int krow = nh * 16 + (L & 7) + ((L >> 4) << 3);
                const int kcol = ks * 16 + (((L >> 3) & 1) << 3);
                ldsm4(smem_u32(sK + krow * TSTR + kcol), kb[nh][0], kb[nh][1], kb[nh][2], kb[nh][3]);
            }
#pragma unroll
            for (int nf = 0; nf < 8; nf++) {
                uint32_t b0 = kb[nf >> 1][(nf & 1) * 2], b1 = kb[nf >> 1][(nf & 1) * 2 + 1];
                mma16816(sc[nf], qf[ks][0], qf[ks][1], qf[ks][2], qf[ks][3], b0, b1);
            }
        }

        // skip-max softmax: p = exp2(s + mask*log2e), lane-local sums
        const float* mg = m2 + (size_t)b * S_LEN + kt * 64;
#pragma unroll
        for (int nf = 0; nf < 8; nf++) {
            const int c0 = nf * 8 + 2 * (L & 3);
            const float m0v = mg[c0], m1v = mg[c0 + 1];
            sc[nf][0] = fexp2(sc[nf][0] + m0v);
            sc[nf][1] = fexp2(sc[nf][1] + m1v);
            sc[nf][2] = fexp2(sc[nf][2] + m0v);
            sc[nf][3] = fexp2(sc[nf][3] + m1v);
            lrow0 += sc[nf][0] + sc[nf][1];
            lrow1 += sc[nf][2] + sc[nf][3];
        }

        // P @ V
#pragma unroll
        for (int ks = 0; ks < 4; ks++) {
            uint32_t a0 = fpack2(sc[2*ks][0],   sc[2*ks][1]);
            uint32_t a1 = fpack2(sc[2*ks][2],   sc[2*ks][3]);
            uint32_t a2 = fpack2(sc[2*ks+1][0], sc[2*ks+1][1]);
            uint32_t a3 = fpack2(sc[2*ks+1][2], sc[2*ks+1][3]);
            uint32_t vb[4][4];
#pragma unroll
            for (int dh = 0; dh < 4; dh++) {
                const int vrow = ks * 16 + (L & 15);
                const int vcol = dh * 16 + ((L >> 4) << 3);
                ldsm4t(smem_u32(sV + vrow * TSTR + vcol), vb[dh][0], vb[dh][1], vb[dh][2], vb[dh][3]);
            }
#pragma unroll
            for (int df = 0; df < 8; df++) {
                uint32_t b0 = vb[df >> 1][(df & 1) * 2], b1 = vb[df >> 1][(df & 1) * 2 + 1];
                mma16816(oacc[df], a0, a1, a2, a3, b0, b1);
            }
        }

        __syncthreads();
        if (kt + 2 < S_LEN / 64)
            attn_issue_kv(dsm, kh, vh, kt + 2, kt & 1, base, t);
        CP_COMMIT;
    }

    // one cross-lane reduction for l
    lrow0 += __shfl_xor_sync(0xffffffffu, lrow0, 1);
    lrow0 += __shfl_xor_sync(0xffffffffu, lrow0, 2);
    lrow1 += __shfl_xor_sync(0xffffffffu, lrow1, 1);
    lrow1 += __shfl_xor_sync(0xffffffffu, lrow1, 2);

    const float inv0 = 1.f / lrow0, inv1 = 1.f / lrow1;
    const int r0 = s0 + w * 16 + (L >> 2);
#pragma unroll
    for (int df = 0; df < 8; df++) {
        const int d = df * 8 + 2 * (L & 3);
        const size_t i0 = (size_t)r0 * ROWB + base + d;
        const size_t i1 = i0 + 8 * ROWB;
        *(uint32_t*)&ch_[i0] = fpack2(oacc[df][0] * inv0, oacc[df][1] * inv0);
        *(uint32_t*)&ch_[i1] = fpack2(oacc[df][2] * inv1, oacc[df][3] * inv1);
    }
}

// =================================================================
// LayerNorm: warp per row (COALESCED: lane*4 within 128-col slabs),
// 8 rows/block, no barrier; emits fp32 + fp16
// =================================================================
__global__ __launch_bounds__(256)
void ln_kernel(const float* __restrict__ X, const float* __restrict__ gamma,
               const float* __restrict__ beta, float* __restrict__ out,
               h16* __restrict__ oh)
{
    const int lane = threadIdx.x & 31, wid = threadIdx.x >> 5;
    const int row  = blockIdx.x * 8 + wid;
    const float* x = X + (size_t)row * HID + lane * 4;

    float4 v[8];
    float s = 0.f, sq = 0.f;
#pragma unroll
    for (int i = 0; i < 8; i++) {
        v[i] = *(const float4*)(x + i * 128);
        s  += v[i].x + v[i].y + v[i].z + v[i].w;
        sq += v[i].x*v[i].x + v[i].y*v[i].y + v[i].z*v[i].z + v[i].w*v[i].w;
    }
#pragma unroll
    for (int off = 16; off; off >>= 1) {
        s  += __shfl_xor_sync(0xffffffffu, s,  off);
        sq += __shfl_xor_sync(0xffffffffu, sq, off);
    }
    const float mean = s * (1.f/1024.f);
    const float var  = sq * (1.f/1024.f) - mean * mean;
    const float rstd = rsqrtf(var + 1e-12f);

    const float* gp = gamma + lane * 4;
    const float* bp = beta  + lane * 4;
    float* op = out + (size_t)row * HID + lane * 4;
    h16*  hp = oh  + (size_t)row * HID + lane * 4;
#pragma unroll
    for (int i = 0; i < 8; i++) {
        float4 g  = *(const float4*)(gp + i * 128);
        float4 bb = *(const float4*)(bp + i * 128);
        float4 o;
        o.x = (v[i].x - mean) * rstd * g.x + bb.x;
        o.y = (v[i].y - mean) * rstd * g.y + bb.y;
        o.z = (v[i].z - mean) * rstd * g.z + bb.z;
        o.w = (v[i].w - mean) * rstd * g.w + bb.w;
        *(float4*)(op + i * 128) = o;
        *(uint32_t*)(hp + i * 128)     = fpack2(o.x, o.y);
        *(uint32_t*)(hp + i * 128 + 2) = fpack2(o.z, o.w);
    }
}

// ---------------- conversion kernels ----------------
__global__ void wconv_kernel(const float* __restrict__ w0, const float* __restrict__ w1,
                             const float* __restrict__ w2, const float* __restrict__ w3,
                             h16* __restrict__ wdst)
{
    const float* src;
    const int m = blockIdx.y;
    if (m == 0) src = w0; else if (m == 1) src = w1; else if (m == 2) src = w2; else src = w3;
    const size_t off = (size_t)m * WELEM;
    for (size_t i = (size_t)blockIdx.x * blockDim.x + threadIdx.x; i < (size_t)WELEM;
         i += (size_t)gridDim.x * blockDim.x) {
        wdst[off + i] = __float2half_rn(src[i]);
    }
}

__global__ void xconv_kernel(const float* __restrict__ in, float* __restrict__ xo,
                             h16* __restrict__ xh,
                             const float* __restrict__ mask, float* __restrict__ m2)
{
    const size_t gid = (size_t)blockIdx.x * blockDim.x + threadIdx.x;
    if (gid < (size_t)BATCH * S_LEN)
        m2[gid] = mask[gid] * LOG2E;
    for (size_t i = gid; i < (size_t)NELEM;
         i += (size_t)gridDim.x * blockDim.x) {
        float v = in[i];
        xo[i] = v;
        xh[i] = __float2half_rn(v);
    }
}

// =================================================================
extern "C" void kernel_launch(void* const* d_in, const int* in_sizes, int n_in,
                              void* d_out, int out_size)
{
    const float* input = (const float*)d_in[0];
    const float* mask  = (const float*)d_in[1];
    const float* Wq = (const float*)d_in[2];
    const float* bq = (const float*)d_in[3];
    const float* Wk = (const float*)d_in[4];
    const float* bk = (const float*)d_in[5];
    const float* Wv = (const float*)d_in[6];
    const float* bv = (const float*)d_in[7];
    const float* Wo = (const float*)d_in[8];
    const float* bo = (const float*)d_in[9];
    const float* gamma = (const float*)d_in[10];
    const float* beta  = (const float*)d_in[11];

    float *x, *y, *m2; h16 *xh, *qh, *kh, *vh, *ch, *wv;
    cudaGetSymbolAddress((void**)&x,  g_x);  cudaGetSymbolAddress((void**)&y,  g_y);
    cudaGetSymbolAddress((void**)&m2, g_m2);
    cudaGetSymbolAddress((void**)&xh, g_xh);
    cudaGetSymbolAddress((void**)&qh, g_qh);
    cudaGetSymbolAddress((void**)&kh, g_kh); cudaGetSymbolAddress((void**)&vh, g_vh);
    cudaGetSymbolAddress((void**)&ch, g_ch);
    cudaGetSymbolAddress((void**)&wv, g_w);

    cudaFuncSetAttribute(attn_f16,     cudaFuncAttributeMaxDynamicSharedMemorySize, ATTN_SMEM);
    cudaFuncSetAttribute(qkv_kernel,   cudaFuncAttributeMaxDynamicSharedMemorySize, GEMM_SMEM);
    cudaFuncSetAttribute(oproj_kernel, cudaFuncAttributeMaxDynamicSharedMemorySize, GEMM_SMEM);

    wconv_kernel<<<dim3(4096, 4), 256>>>(Wq, Wk, Wv, Wo, wv);
    xconv_kernel<<<4096, 256>>>(input, x, xh, mask, m2);

    for (int l = 0; l < NLAYER; l++) {
        const size_t wq_o = (size_t)(0 * NLAYER + l) * HID * HID;
        const size_t wo_o = (size_t)(3 * NLAYER + l) * HID * HID;
        const size_t voff = (size_t)l * HID;

        qkv_kernel<<<dim3(8, 32, 3), 256, GEMM_SMEM>>>(
            xh, wv + wq_o,
            bq + voff, bk + voff, bv + voff,
            qh, kh, vh);

        attn_f16<<<dim3(S_LEN / QT, BATCH * NHEAD), 256, ATTN_SMEM>>>(
            qh, kh, vh, m2, ch);

        oproj_kernel<<<dim3(8, 32), 256, GEMM_SMEM>>>(ch, wv + wo_o,
                                                      bo + voff, x, y);

        float* dst = (l == NLAYER - 1) ? (float*)d_out : x;
        ln_kernel<<<M_ROWS / 8, 256>>>(y, gamma + voff, beta + voff, dst, xh);
    }
}

// round 16
// speedup vs baseline: 1.1332x; 1.0029x over previous
#include <cuda_runtime.h>
#include <cuda_fp16.h>
#include <cstdint>

#define S_LEN  2048
#define BATCH  2
#define HID    1024
#define NHEAD  16
#define HDIM   64
#define NLAYER 12
#define M_ROWS (S_LEN*BATCH)   // 4096
#define ROWB   (BATCH*HID)     // 2048
#define NELEM  (M_ROWS*HID)
#define WELEM  (NLAYER*HID*HID)

typedef __half h16;

// ---------------- scratch ----------------
__device__ float g_x [NELEM];
__device__ float g_y [NELEM];
__device__ float g_m2[BATCH*S_LEN];        // mask * log2e
__device__ h16  g_xh[NELEM];
__device__ h16  g_qh[NELEM];
__device__ h16  g_kh[NELEM];
__device__ h16  g_vh[NELEM];
__device__ h16  g_ch[NELEM];
__device__ h16  g_w [4ull*WELEM];

// ---------------- helpers ----------------
__device__ __forceinline__ uint32_t smem_u32(const void* p) {
    return (uint32_t)__cvta_generic_to_shared(p);
}
__device__ __forceinline__ void cp16(void* s, const void* g) {
    asm volatile("cp.async.cg.shared.global [%0], [%1], 16;"
        :: "r"(smem_u32(s)), "l"(g));
}
#define CP_COMMIT asm volatile("cp.async.commit_group;")
#define CP_WAIT(N) asm volatile("cp.async.wait_group %0;" :: "n"(N))

__device__ __forceinline__ void ldsm4(uint32_t a, uint32_t& r0, uint32_t& r1, uint32_t& r2, uint32_t& r3) {
    asm volatile("ldmatrix.sync.aligned.m8n8.x4.shared.b16 {%0,%1,%2,%3},[%4];"
        : "=r"(r0), "=r"(r1), "=r"(r2), "=r"(r3) : "r"(a));
}
__device__ __forceinline__ void ldsm4t(uint32_t a, uint32_t& r0, uint32_t& r1, uint32_t& r2, uint32_t& r3) {
    asm volatile("ldmatrix.sync.aligned.m8n8.x4.trans.shared.b16 {%0,%1,%2,%3},[%4];"
        : "=r"(r0), "=r"(r1), "=r"(r2), "=r"(r3) : "r"(a));
}
__device__ __forceinline__ void mma16816(float* c, uint32_t a0, uint32_t a1, uint32_t a2, uint32_t a3,
                                         uint32_t b0, uint32_t b1) {
    asm volatile("mma.sync.aligned.m16n8k16.row.col.f32.f16.f16.f32 "
        "{%0,%1,%2,%3},{%4,%5,%6,%7},{%8,%9},{%0,%1,%2,%3};"
        : "+f"(c[0]), "+f"(c[1]), "+f"(c[2]), "+f"(c[3])
        : "r"(a0), "r"(a1), "r"(a2), "r"(a3), "r"(b0), "r"(b1));
}
__device__ __forceinline__ float fexp2(float x) {
    float r;
    asm("ex2.approx.ftz.f32 %0, %1;" : "=f"(r) : "f"(x));
    return r;
}
__device__ __forceinline__ uint32_t fpack2(float x, float y) {
    __half2 p = __floats2half2_rn(x, y);
    return *reinterpret_cast<uint32_t*>(&p);
}

#define LOG2E 1.4426950408889634f
#define SCL2  (0.125f * LOG2E)

// =================================================================
// fp16 GEMM, cp.async double-buffered (exact R11).
// block 128x128, 256 thr = 8 warps (2m x 4n), warp 64x32, KT=32
// =================================================================
#define ASTR 56
#define BSTR 136
#define SA_OFF(st) ((st)*128*ASTR)
#define SB_BASE (2*128*ASTR)
#define SB_OFF(st) (SB_BASE + (st)*32*BSTR)
#define GEMM_SMEM ((2*128*ASTR + 2*32*BSTR)*(int)sizeof(h16))  // 46080

__device__ __forceinline__ void gemm_issue(
    h16* dsm, const h16* __restrict__ A, const h16* __restrict__ W,
    int m0, int n0, int k0, int st, int t)
{
    const int ar = t >> 1, ac = (t & 1) * 16;
    const size_t ga = (size_t)(m0 + ar) * HID + k0 + ac;
    h16* a0 = dsm + SA_OFF(st) + ar * ASTR + ac;
    cp16(a0, A + ga); cp16(a0 + 8, A + ga + 8);
    const int br = t >> 3, bc = (t & 7) * 16;
    const size_t gb = (size_t)(k0 + br) * HID + n0 + bc;
    h16* b0 = dsm + SB_OFF(st) + br * BSTR + bc;
    cp16(b0, W + gb); cp16(b0 + 8, W + gb + 8);
}

__device__ __forceinline__ void gemm_core(
    const h16* __restrict__ A, const h16* __restrict__ W, float acc[4][4][4])
{
    extern __shared__ h16 dsm[];
    const int t = threadIdx.x;
    const int L = t & 31, w = t >> 5;
    const int wm = (w >> 2) * 64, wn = (w & 3) * 32;
    const int m0 = blockIdx.y * 128, n0 = blockIdx.x * 128;

#pragma unroll
    for (int i = 0; i < 4; i++)
#pragma unroll
        for (int j = 0; j < 4; j++)
#pragma unroll
            for (int r = 0; r < 4; r++) acc[i][j][r] = 0.f;

    gemm_issue(dsm, A, W, m0, n0, 0,  0, t); CP_COMMIT;
    gemm_issue(dsm, A, W, m0, n0, 32, 1, t); CP_COMMIT;

    for (int ko = 0; ko < HID / 32; ko++) {
        CP_WAIT(1);
        __syncthreads();
        const int st = ko & 1;
        const h16* cA = dsm + SA_OFF(st);
        const h16* cB = dsm + SB_OFF(st);
#pragma unroll
        for (int ks = 0; ks < 2; ks++) {
            const int kk = ks * 16;
            uint32_t bb[2][4];
#pragma unroll
            for (int nh = 0; nh < 2; nh++) {
                const int brow = kk + (L & 15);
                const int bcol = wn + nh * 16 + ((L >> 4) << 3);
                ldsm4t(smem_u32(cB + brow * BSTR + bcol), bb[nh][0], bb[nh][1], bb[nh][2], bb[nh][3]);
            }
#pragma unroll
            for (int mf = 0; mf < 4; mf++) {
                const int arow = wm + mf * 16 + (L & 15);
                const int acol = kk + ((L >> 4) << 3);
                uint32_t a0, a1, a2, a3;
                ldsm4(smem_u32(cA + arow * ASTR + acol), a0, a1, a2, a3);
#pragma unroll
                for (int nf = 0; nf < 4; nf++) {
                    uint32_t b0 = bb[nf >> 1][(nf & 1) * 2], b1 = bb[nf >> 1][(nf & 1) * 2 + 1];
                    mma16816(acc[mf][nf], a0, a1, a2, a3, b0, b1);
                }
            }
        }
        __syncthreads();
        if (ko + 2 < HID / 32)
            gemm_issue(dsm, A, W, m0, n0, (ko + 2) * 32, st, t);
        CP_COMMIT;
    }
}

// z=0: Q output, scaled by SCL2. z=1: K. z=2: V.
__global__ __launch_bounds__(256, 2)
void qkv_kernel(const h16* __restrict__ xh,
                const h16* __restrict__ wbase,
                const float* __restrict__ bq, const float* __restrict__ bk, const float* __restrict__ bv,
                h16* __restrict__ qh, h16* __restrict__ kh, h16* __restrict__ vh)
{
    const int z = blockIdx.z;
    const h16* W = wbase + (size_t)z * NLAYER * HID * HID;
    const float* bias = (z == 0) ? bq : (z == 1) ? bk : bv;
    h16* out = (z == 0) ? qh : (z == 1) ? kh : vh;
    const float scl = (z == 0) ? SCL2 : 1.0f;

    float acc[4][4][4];
    gemm_core(xh, W, acc);

    const int t = threadIdx.x, L = t & 31, w = t >> 5;
    const int wm = (w >> 2) * 64, wn = (w & 3) * 32;
    const int m0 = blockIdx.y * 128, n0 = blockIdx.x * 128;
#pragma unroll
    for (int mf = 0; mf < 4; mf++) {
        const int r0 = m0 + wm + mf * 16 + (L >> 2);
#pragma unroll
        for (int nf = 0; nf < 4; nf++) {
            const int c = n0 + wn + nf * 8 + 2 * (L & 3);
            const float b0 = bias[c], b1 = bias[c + 1];
            *(uint32_t*)&out[(size_t)r0 * HID + c] =
                fpack2((acc[mf][nf][0] + b0) * scl, (acc[mf][nf][1] + b1) * scl);
            *(uint32_t*)&out[(size_t)(r0 + 8) * HID + c] =
                fpack2((acc[mf][nf][2] + b0) * scl, (acc[mf][nf][3] + b1) * scl);
        }
    }
}

__global__ __launch_bounds__(256, 2)
void oproj_kernel(const h16* __restrict__ ch_, const h16* __restrict__ W,
                  const float* __restrict__ bias, const float* __restrict__ res,
                  float* __restrict__ y)
{
    float acc[4][4][4];
    gemm_core(ch_, W, acc);

    const int t = threadIdx.x, L = t & 31, w = t >> 5;
    const int wm = (w >> 2) * 64, wn = (w & 3) * 32;
    const int m0 = blockIdx.y * 128, n0 = blockIdx.x * 128;
#pragma unroll
    for (int mf = 0; mf < 4; mf++) {
        const int r0 = m0 + wm + mf * 16 + (L >> 2);
#pragma unroll
        for (int nf = 0; nf < 4; nf++) {
            const int c = n0 + wn + nf * 8 + 2 * (L & 3);
            const float b0 = bias[c], b1 = bias[c + 1];
            float2 rv0 = *(const float2*)&res[(size_t)r0 * HID + c];
            float2 rv1 = *(const float2*)&res[(size_t)(r0 + 8) * HID + c];
            float2 o0 = { acc[mf][nf][0] + b0 + rv0.x, acc[mf][nf][1] + b1 + rv0.y };
            float2 o1 = { acc[mf][nf][2] + b0 + rv1.x, acc[mf][nf][3] + b1 + rv1.y };
            *(float2*)&y[(size_t)r0 * HID + c]       = o0;
            *(float2*)&y[(size_t)(r0 + 8) * HID + c] = o1;
        }
    }
}

// =================================================================
// Flash attention fp16 (EXACT R11): 256 thr (8 warps), 16 Q rows/warp,
// QT=128, K-tile 64, 2-stage cp.async KV pipeline, skip-max softmax.
// =================================================================
#define TSTR 72
#define QT   128
#define AT_Q  0
#define AT_ST(st) (QT*TSTR + (st)*2*64*TSTR)
#define AT_V  (64*TSTR)
#define ATTN_SMEM ((QT*TSTR + 4*64*TSTR)*(int)sizeof(h16))  // 55296

__device__ __forceinline__ void attn_issue_kv(
    h16* dsm, const h16* __restrict__ kh, const h16* __restrict__ vh,
    int kt, int st, int base, int t)
{
    const int row = t >> 2, c4 = (t & 3) * 16;
    const size_t g = (size_t)(kt * 64 + row) * ROWB + base + c4;
    h16* s = dsm + AT_ST(st);
    h16* pk = s +        row * TSTR + c4;
    h16* pv = s + AT_V + row * TSTR + c4;
    cp16(pk, kh + g); cp16(pk + 8, kh + g + 8);
    cp16(pv, vh + g); cp16(pv + 8, vh + g + 8);
}

__global__ __launch_bounds__(256, 2)
void attn_f16(const h16* __restrict__ qh,
              const h16* __restrict__ kh, const h16* __restrict__ vh,
              const float* __restrict__ m2,
              h16* __restrict__ ch_)
{
    extern __shared__ h16 dsm[];
    const int t = threadIdx.x, L = t & 31, w = t >> 5;
    const int s0 = blockIdx.x * QT;
    const int b  = blockIdx.y >> 4, h = blockIdx.y & 15;
    const int base = b * HID + h * HDIM;

    {
        const int row = t >> 1, cc = (t & 1) * 32;
        const size_t g = (size_t)(s0 + row) * ROWB + base + cc;
        h16* pq = dsm + AT_Q + row * TSTR + cc;
#pragma unroll
        for (int c = 0; c < 4; c++)
            cp16(pq + c * 8, qh + g + c * 8);
    }
    CP_COMMIT;
    attn_issue_kv(dsm, kh, vh, 0, 0, base, t); CP_COMMIT;
    attn_issue_kv(dsm, kh, vh, 1, 1, base, t); CP_COMMIT;

    CP_WAIT(2);
    __syncthreads();

    uint32_t qf[4][4];
#pragma unroll
    for (int ks = 0; ks < 4; ks++) {
        const int qrow = w * 16 + (L & 15);
        const int qcol = ks * 16 + ((L >> 4) << 3);
        ldsm4(smem_u32(dsm + AT_Q + qrow * TSTR + qcol), qf[ks][0], qf[ks][1], qf[ks][2], qf[ks][3]);
    }

    float oacc[8][4];
#pragma unroll
    for (int i = 0; i < 8; i++)
#pragma unroll
        for (int j = 0; j < 4; j++) oacc[i][j] = 0.f;
    float lrow0 = 0.f, lrow1 = 0.f;   // lane-local partial sums

    for (int kt = 0; kt < S_LEN / 64; kt++) {
        CP_WAIT(1);
        __syncthreads();
        const h16* s  = dsm + AT_ST(kt & 1);
        const h16* sK = s;
        const h16* sV = s + AT_V;

        float sc[8][4];
#pragma unroll
        for (int i = 0; i < 8; i++)
#pragma unroll
            for (int j = 0; j < 4; j++) sc[i][j] = 0.f;

#pragma unroll
        for (int ks = 0; ks < 4; ks++) {
            uint32_t kb[4][4];
#pragma unroll
            for (int nh = 0; nh < 4; nh++) {
                const int krow = nh * 16 + (L & 7) + ((L >> 4) << 3);
                const int kcol = ks * 16 + (((L >> 3) & 1) << 3);
                ldsm4(smem_u32(sK + krow * TSTR + kcol), kb[nh][0], kb[nh][1], kb[nh][2], kb[nh][3]);
            }
#pragma unroll
            for (int nf = 0; nf < 8; nf++) {
                uint32_t b0 = kb[nf >> 1][(nf & 1) * 2], b1 = kb[nf >> 1][(nf & 1) * 2 + 1];
                mma16816(sc[nf], qf[ks][0], qf[ks][1], qf[ks][2], qf[ks][3], b0, b1);
            }
        }

        // skip-max softmax: p = exp2(s + mask*log2e), lane-local sums
        const float* mg = m2 + (size_t)b * S_LEN + kt * 64;
#pragma unroll
        for (int nf = 0; nf < 8; nf++) {
            const int c0 = nf * 8 + 2 * (L & 3);
            const float m0v = mg[c0], m1v = mg[c0 + 1];
            sc[nf][0] = fexp2(sc[nf][0] + m0v);
            sc[nf][1] = fexp2(sc[nf][1] + m1v);
            sc[nf][2] = fexp2(sc[nf][2] + m0v);
            sc[nf][3] = fexp2(sc[nf][3] + m1v);
            lrow0 += sc[nf][0] + sc[nf][1];
            lrow1 += sc[nf][2] + sc[nf][3];
        }

        // P @ V
#pragma unroll
        for (int ks = 0; ks < 4; ks++) {
            uint32_t a0 = fpack2(sc[2*ks][0],   sc[2*ks][1]);
            uint32_t a1 = fpack2(sc[2*ks][2],   sc[2*ks][3]);
            uint32_t a2 = fpack2(sc[2*ks+1][0], sc[2*ks+1][1]);
            uint32_t a3 = fpack2(sc[2*ks+1][2], sc[2*ks+1][3]);
            uint32_t vb[4][4];
#pragma unroll
            for (int dh = 0; dh < 4; dh++) {
                const int vrow = ks * 16 + (L & 15);
                const int vcol = dh * 16 + ((L >> 4) << 3);
                ldsm4t(smem_u32(sV + vrow * TSTR + vcol), vb[dh][0], vb[dh][1], vb[dh][2], vb[dh][3]);
            }
#pragma unroll
            for (int df = 0; df < 8; df++) {
                uint32_t b0 = vb[df >> 1][(df & 1) * 2], b1 = vb[df >> 1][(df & 1) * 2 + 1];
                mma16816(oacc[df], a0, a1, a2, a3, b0, b1);
            }
        }

        __syncthreads();
        if (kt + 2 < S_LEN / 64)
            attn_issue_kv(dsm, kh, vh, kt + 2, kt & 1, base, t);
        CP_COMMIT;
    }

    // one cross-lane reduction for l
    lrow0 += __shfl_xor_sync(0xffffffffu, lrow0, 1);
    lrow0 += __shfl_xor_sync(0xffffffffu, lrow0, 2);
    lrow1 += __shfl_xor_sync(0xffffffffu, lrow1, 1);
    lrow1 += __shfl_xor_sync(0xffffffffu, lrow1, 2);

    const float inv0 = 1.f / lrow0, inv1 = 1.f / lrow1;
    const int r0 = s0 + w * 16 + (L >> 2);
#pragma unroll
    for (int df = 0; df < 8; df++) {
        const int d = df * 8 + 2 * (L & 3);
        const size_t i0 = (size_t)r0 * ROWB + base + d;
        const size_t i1 = i0 + 8 * ROWB;
        *(uint32_t*)&ch_[i0] = fpack2(oacc[df][0] * inv0, oacc[df][1] * inv0);
        *(uint32_t*)&ch_[i1] = fpack2(oacc[df][2] * inv1, oacc[df][3] * inv1);
    }
}

// =================================================================
// LayerNorm: warp per row (coalesced), 8 rows/block, no barrier
// =================================================================
__global__ __launch_bounds__(256)
void ln_kernel(const float* __restrict__ X, const float* __restrict__ gamma,
               const float* __restrict__ beta, float* __restrict__ out,
               h16* __restrict__ oh)
{
    const int lane = threadIdx.x & 31, wid = threadIdx.x >> 5;
    const int row  = blockIdx.x * 8 + wid;
    const float* x = X + (size_t)row * HID + lane * 4;

    float4 v[8];
    float s = 0.f, sq = 0.f;
#pragma unroll
    for (int i = 0; i < 8; i++) {
        v[i] = *(const float4*)(x + i * 128);
        s  += v[i].x + v[i].y + v[i].z + v[i].w;
        sq += v[i].x*v[i].x + v[i].y*v[i].y + v[i].z*v[i].z + v[i].w*v[i].w;
    }
#pragma unroll
    for (int off = 16; off; off >>= 1) {
        s  += __shfl_xor_sync(0xffffffffu, s,  off);
        sq += __shfl_xor_sync(0xffffffffu, sq, off);
    }
    const float mean = s * (1.f/1024.f);
    const float var  = sq * (1.f/1024.f) - mean * mean;
    const float rstd = rsqrtf(var + 1e-12f);

    const float* gp = gamma + lane * 4;
    const float* bp = beta  + lane * 4;
    float* op = out + (size_t)row * HID + lane * 4;
    h16*  hp = oh  + (size_t)row * HID + lane * 4;
#pragma unroll
    for (int i = 0; i < 8; i++) {
        float4 g  = *(const float4*)(gp + i * 128);
        float4 bb = *(const float4*)(bp + i * 128);
        float4 o;
        o.x = (v[i].x - mean) * rstd * g.x + bb.x;
        o.y = (v[i].y - mean) * rstd * g.y + bb.y;
        o.z = (v[i].z - mean) * rstd * g.z + bb.z;
        o.w = (v[i].w - mean) * rstd * g.w + bb.w;
        *(float4*)(op + i * 128) = o;
        *(uint32_t*)(hp + i * 128)     = fpack2(o.x, o.y);
        *(uint32_t*)(hp + i * 128 + 2) = fpack2(o.z, o.w);
    }
}

// ---------------- conversion kernels (vectorized x4) ----------------
__global__ void wconv_kernel(const float* __restrict__ w0, const float* __restrict__ w1,
                             const float* __restrict__ w2, const float* __restrict__ w3,
                             h16* __restrict__ wdst)
{
    const float* src;
    const int m = blockIdx.y;
    if (m == 0) src = w0; else if (m == 1) src = w1; else if (m == 2) src = w2; else src = w3;
    const size_t off4 = (size_t)m * (WELEM / 4);
    const float4* s4 = (const float4*)src;
    uint2* d4 = (uint2*)wdst + off4;
    for (size_t i = (size_t)blockIdx.x * blockDim.x + threadIdx.x; i < (size_t)(WELEM / 4);
         i += (size_t)gridDim.x * blockDim.x) {
        float4 v = s4[i];
        uint2 o;
        o.x = fpack2(v.x, v.y);
        o.y = fpack2(v.z, v.w);
        d4[i] = o;
    }
}

__global__ void xconv_kernel(const float* __restrict__ in, float* __restrict__ xo,
                             h16* __restrict__ xh,
                             const float* __restrict__ mask, float* __restrict__ m2)
{
    const size_t gid = (size_t)blockIdx.x * blockDim.x + threadIdx.x;
    if (gid < (size_t)BATCH * S_LEN)
        m2[gid] = mask[gid] * LOG2E;
    const float4* s4 = (const float4*)in;
    float4* x4 = (float4*)xo;
    uint2* h4 = (uint2*)xh;
    for (size_t i = gid; i < (size_t)(NELEM / 4);
         i += (size_t)gridDim.x * blockDim.x) {
        float4 v = s4[i];
        x4[i] = v;
        uint2 o;
        o.x = fpack2(v.x, v.y);
        o.y = fpack2(v.z, v.w);
        h4[i] = o;
    }
}

// =================================================================
extern "C" void kernel_launch(void* const* d_in, const int* in_sizes, int n_in,
                              void* d_out, int out_size)
{
    const float* input = (const float*)d_in[0];
    const float* mask  = (const float*)d_in[1];
    const float* Wq = (const float*)d_in[2];
    const float* bq = (const float*)d_in[3];
    const float* Wk = (const float*)d_in[4];
    const float* bk = (const float*)d_in[5];
    const float* Wv = (const float*)d_in[6];
    const float* bv = (const float*)d_in[7];
    const float* Wo = (const float*)d_in[8];
    const float* bo = (const float*)d_in[9];
    const float* gamma = (const float*)d_in[10];
    const float* beta  = (const float*)d_in[11];

    float *x, *y, *m2; h16 *xh, *qh, *kh, *vh, *ch, *wv;
    cudaGetSymbolAddress((void**)&x,  g_x);  cudaGetSymbolAddress((void**)&y,  g_y);
    cudaGetSymbolAddress((void**)&m2, g_m2);
    cudaGetSymbolAddress((void**)&xh, g_xh);
    cudaGetSymbolAddress((void**)&qh, g_qh);
    cudaGetSymbolAddress((void**)&kh, g_kh); cudaGetSymbolAddress((void**)&vh, g_vh);
    cudaGetSymbolAddress((void**)&ch, g_ch);
    cudaGetSymbolAddress((void**)&wv, g_w);

    cudaFuncSetAttribute(attn_f16,     cudaFuncAttributeMaxDynamicSharedMemorySize, ATTN_SMEM);
    cudaFuncSetAttribute(qkv_kernel,   cudaFuncAttributeMaxDynamicSharedMemorySize, GEMM_SMEM);
    cudaFuncSetAttribute(oproj_kernel, cudaFuncAttributeMaxDynamicSharedMemorySize, GEMM_SMEM);

    wconv_kernel<<<dim3(2048, 4), 256>>>(Wq, Wk, Wv, Wo, wv);
    xconv_kernel<<<4096, 256>>>(input, x, xh, mask, m2);

    for (int l = 0; l < NLAYER; l++) {
        const size_t wq_o = (size_t)(0 * NLAYER + l) * HID * HID;
        const size_t wo_o = (size_t)(3 * NLAYER + l) * HID * HID;
        const size_t voff = (size_t)l * HID;

        qkv_kernel<<<dim3(8, 32, 3), 256, GEMM_SMEM>>>(
            xh, wv + wq_o,
            bq + voff, bk + voff, bv + voff,
            qh, kh, vh);

        attn_f16<<<dim3(S_LEN / QT, BATCH * NHEAD), 256, ATTN_SMEM>>>(
            qh, kh, vh, m2, ch);

        oproj_kernel<<<dim3(8, 32), 256, GEMM_SMEM>>>(ch, wv + wo_o,
                                                      bo + voff, x, y);

        float* dst = (l == NLAYER - 1) ? (float*)d_out : x;
        ln_kernel<<<M_ROWS / 8, 256>>>(y, gamma + voff, beta + voff, dst, xh);
    }
}